// round 1
// baseline (speedup 1.0000x reference)
#include <cuda_runtime.h>

#define D          256
#define NCLS       4

// Scratch (no allocs allowed): re-zeroed at the start of every launch.
__device__ float g_sums[NCLS * D];
__device__ int   g_counts[NCLS];
__device__ int   g_lab_stride;   // 1 = labels are int32, 2 = labels are int64 (read low word)

// ---------------------------------------------------------------------------
// Kernel 1: zero scratch + detect label element width.
// For int64 labels (little-endian), every odd 32-bit word is the zero high
// half. For int32 labels in [0,4), the odds of 256 consecutive odd-indexed
// labels all being 0 is (1/4)^256 ~ 0.
// ---------------------------------------------------------------------------
__global__ void detect_and_zero(const unsigned int* __restrict__ labw) {
    int tid = threadIdx.x;
    for (int i = tid; i < NCLS * D; i += blockDim.x) g_sums[i] = 0.0f;
    if (tid < NCLS) g_counts[tid] = 0;

    __shared__ int any;
    if (tid == 0) any = 0;
    __syncthreads();
    if (labw[2 * tid + 1] != 0u) atomicOr(&any, 1);
    __syncthreads();
    if (tid == 0) g_lab_stride = any ? 1 : 2;
}

// ---------------------------------------------------------------------------
// Kernel 2: streaming per-class accumulation.
// blockDim = 256 laid out as (x:64 float4-columns, y:4 rows). Each warp sees
// a single row -> label load is a broadcast. Per element: 4 masked FFMAs.
// ---------------------------------------------------------------------------
__global__ void __launch_bounds__(256) accum_kernel(
    const float4* __restrict__ feat,          // [rows, 64] float4
    const unsigned int* __restrict__ labw,    // label words
    int rows)
{
    const int x = threadIdx.x & 63;   // float4 column group 0..63
    const int y = threadIdx.x >> 6;   // row lane 0..3
    const int ls = g_lab_stride;      // uniform

    float4 a0 = make_float4(0.f, 0.f, 0.f, 0.f);
    float4 a1 = a0, a2 = a0, a3 = a0;
    int c0 = 0, c1 = 0, c2 = 0, c3 = 0;

    const long long stride = (long long)gridDim.x * 4;
    for (long long r = (long long)blockIdx.x * 4 + y; r < rows; r += stride) {
        const int   lab = (int)labw[r * ls];
        const float4 v  = feat[r * 64 + x];

        const float w0 = (lab == 0) ? 1.0f : 0.0f;
        const float w1 = (lab == 1) ? 1.0f : 0.0f;
        const float w2 = (lab == 2) ? 1.0f : 0.0f;
        const float w3 = (lab == 3) ? 1.0f : 0.0f;

        a0.x = fmaf(v.x, w0, a0.x); a0.y = fmaf(v.y, w0, a0.y);
        a0.z = fmaf(v.z, w0, a0.z); a0.w = fmaf(v.w, w0, a0.w);
        a1.x = fmaf(v.x, w1, a1.x); a1.y = fmaf(v.y, w1, a1.y);
        a1.z = fmaf(v.z, w1, a1.z); a1.w = fmaf(v.w, w1, a1.w);
        a2.x = fmaf(v.x, w2, a2.x); a2.y = fmaf(v.y, w2, a2.y);
        a2.z = fmaf(v.z, w2, a2.z); a2.w = fmaf(v.w, w2, a2.w);
        a3.x = fmaf(v.x, w3, a3.x); a3.y = fmaf(v.y, w3, a3.y);
        a3.z = fmaf(v.z, w3, a3.z); a3.w = fmaf(v.w, w3, a3.w);

        if (x == 0) {
            c0 += (lab == 0); c1 += (lab == 1);
            c2 += (lab == 2); c3 += (lab == 3);
        }
    }

    // Block-level reduction in shared, then one global atomic per entry.
    __shared__ float s[NCLS][D];
    __shared__ int   sc[NCLS];
    const int tid = threadIdx.x;
    for (int i = tid; i < NCLS * D; i += 256) ((float*)s)[i] = 0.0f;
    if (tid < NCLS) sc[tid] = 0;
    __syncthreads();

    const int col = 4 * x;
    atomicAdd(&s[0][col + 0], a0.x); atomicAdd(&s[0][col + 1], a0.y);
    atomicAdd(&s[0][col + 2], a0.z); atomicAdd(&s[0][col + 3], a0.w);
    atomicAdd(&s[1][col + 0], a1.x); atomicAdd(&s[1][col + 1], a1.y);
    atomicAdd(&s[1][col + 2], a1.z); atomicAdd(&s[1][col + 3], a1.w);
    atomicAdd(&s[2][col + 0], a2.x); atomicAdd(&s[2][col + 1], a2.y);
    atomicAdd(&s[2][col + 2], a2.z); atomicAdd(&s[2][col + 3], a2.w);
    atomicAdd(&s[3][col + 0], a3.x); atomicAdd(&s[3][col + 1], a3.y);
    atomicAdd(&s[3][col + 2], a3.z); atomicAdd(&s[3][col + 3], a3.w);
    if (x == 0) {
        atomicAdd(&sc[0], c0); atomicAdd(&sc[1], c1);
        atomicAdd(&sc[2], c2); atomicAdd(&sc[3], c3);
    }
    __syncthreads();

    for (int i = tid; i < NCLS * D; i += 256)
        atomicAdd(&g_sums[i], ((float*)s)[i]);
    if (tid < NCLS) atomicAdd(&g_counts[tid], sc[tid]);
}

// ---------------------------------------------------------------------------
// Kernel 3: mean, L2 normalize (eps 1e-12), write centers + target.
// ---------------------------------------------------------------------------
__global__ void finalize_kernel(float* __restrict__ out, int out_size) {
    const int tid = threadIdx.x;   // 0..255 = column
    __shared__ float red[256];
    __shared__ float s_norm;

    for (int c = 0; c < NCLS; c++) {
        const float mean = g_sums[c * D + tid] / (float)g_counts[c];
        red[tid] = mean * mean;
        __syncthreads();
        #pragma unroll
        for (int off = 128; off > 0; off >>= 1) {
            if (tid < off) red[tid] += red[tid + off];
            __syncthreads();
        }
        if (tid == 0) s_norm = fmaxf(sqrtf(red[0]), 1e-12f);
        __syncthreads();
        out[c * D + tid] = mean / s_norm;
        __syncthreads();
    }

    // Second output: target = arange(4), as floats in the tail of d_out.
    if (out_size > NCLS * D) {
        int extra = out_size - NCLS * D;
        if (tid < extra) out[NCLS * D + tid] = (tid < NCLS) ? (float)tid : 0.0f;
    }
}

// ---------------------------------------------------------------------------
extern "C" void kernel_launch(void* const* d_in, const int* in_sizes, int n_in,
                              void* d_out, int out_size) {
    const float4*       feat = (const float4*)d_in[0];
    const unsigned int* labw = (const unsigned int*)d_in[1];
    const int rows = in_sizes[1];

    detect_and_zero<<<1, 256>>>(labw);
    accum_kernel<<<2368, 256>>>(feat, labw, rows);
    finalize_kernel<<<1, 256>>>((float*)d_out, out_size);
}

// round 3
// speedup vs baseline: 1.0235x; 1.0235x over previous
#include <cuda_runtime.h>

#define D    256
#define NCLS 4

// Scratch invariant: zero at kernel_launch entry (zero-initialized at module
// load; finalize_kernel re-zeroes it after consuming). No allocs anywhere.
__device__ float g_sums[NCLS * D];
__device__ int   g_counts[NCLS];

// ---------------------------------------------------------------------------
// Streaming per-class accumulation.
// blockDim 256 = (x: 64 float4 columns) x (y: 4 row-lanes). A warp has a
// single y -> label loads are warp-broadcast. Each thread processes 4 rows
// per iteration with all 8 loads batched up front (MLP ~8).
// ---------------------------------------------------------------------------
__global__ void __launch_bounds__(256) accum_kernel(
    const float4* __restrict__ feat,          // [rows, 64] float4
    const unsigned int* __restrict__ labw,    // label words (int32 or int64)
    int rows)
{
    // Label width detection: int64 (LE) => all odd 32-bit words of the first
    // 64 are zero high-halves. int32 labels in [0,4): P(all zero) ~ 4^-32.
    __shared__ int s_ls;
    if (threadIdx.x < 32) {
        unsigned w = labw[2 * threadIdx.x + 1];
        unsigned any = __ballot_sync(0xffffffffu, w != 0u);
        if (threadIdx.x == 0) s_ls = any ? 1 : 2;
    }
    __syncthreads();
    const long long ls = s_ls;

    const int x = threadIdx.x & 63;
    const int y = threadIdx.x >> 6;

    float4 a0 = make_float4(0.f, 0.f, 0.f, 0.f);
    float4 a1 = a0, a2 = a0, a3 = a0;
    int c0 = 0, c1 = 0, c2 = 0, c3 = 0;

    const float4 z = make_float4(0.f, 0.f, 0.f, 0.f);
    const long long stride = (long long)gridDim.x * 16;

    for (long long base = (long long)blockIdx.x * 16 + y * 4; base < rows;
         base += stride) {
        const bool p1 = base + 1 < rows;
        const bool p2 = base + 2 < rows;
        const bool p3 = base + 3 < rows;

        // Batched independent loads: 4 labels + 4 float4 rows.
        const int l0 =      (int)labw[(base    ) * ls];
        const int l1 = p1 ? (int)labw[(base + 1) * ls] : -1;
        const int l2 = p2 ? (int)labw[(base + 2) * ls] : -1;
        const int l3 = p3 ? (int)labw[(base + 3) * ls] : -1;
        const float4 v0 =      feat[(base    ) * 64 + x];
        const float4 v1 = p1 ? feat[(base + 1) * 64 + x] : z;
        const float4 v2 = p2 ? feat[(base + 2) * 64 + x] : z;
        const float4 v3 = p3 ? feat[(base + 3) * 64 + x] : z;

#define ACCROW(v, l)                                                          \
        {                                                                     \
            const float w0 = ((l) == 0) ? 1.f : 0.f;                          \
            const float w1 = ((l) == 1) ? 1.f : 0.f;                          \
            const float w2 = ((l) == 2) ? 1.f : 0.f;                          \
            const float w3 = ((l) == 3) ? 1.f : 0.f;                          \
            a0.x = fmaf(v.x, w0, a0.x); a0.y = fmaf(v.y, w0, a0.y);           \
            a0.z = fmaf(v.z, w0, a0.z); a0.w = fmaf(v.w, w0, a0.w);           \
            a1.x = fmaf(v.x, w1, a1.x); a1.y = fmaf(v.y, w1, a1.y);           \
            a1.z = fmaf(v.z, w1, a1.z); a1.w = fmaf(v.w, w1, a1.w);           \
            a2.x = fmaf(v.x, w2, a2.x); a2.y = fmaf(v.y, w2, a2.y);           \
            a2.z = fmaf(v.z, w2, a2.z); a2.w = fmaf(v.w, w2, a2.w);           \
            a3.x = fmaf(v.x, w3, a3.x); a3.y = fmaf(v.y, w3, a3.y);           \
            a3.z = fmaf(v.z, w3, a3.z); a3.w = fmaf(v.w, w3, a3.w);           \
        }
        ACCROW(v0, l0) ACCROW(v1, l1) ACCROW(v2, l2) ACCROW(v3, l3)
#undef ACCROW

        if (x == 0) {
            c0 += (l0 == 0) + (l1 == 0) + (l2 == 0) + (l3 == 0);
            c1 += (l0 == 1) + (l1 == 1) + (l2 == 1) + (l3 == 1);
            c2 += (l0 == 2) + (l1 == 2) + (l2 == 2) + (l3 == 2);
            c3 += (l0 == 3) + (l1 == 3) + (l2 == 3) + (l3 == 3);
        }
    }

    // Block reduction: non-atomic smem transpose (unique slots), then one
    // global atomicAdd per (class, column) per block.
    __shared__ float4 s4[4][NCLS][64];     // [y][class][col4] = 16 KB
    __shared__ int    sc[4][NCLS];
    s4[y][0][x] = a0; s4[y][1][x] = a1; s4[y][2][x] = a2; s4[y][3][x] = a3;
    if (x == 0) { sc[y][0] = c0; sc[y][1] = c1; sc[y][2] = c2; sc[y][3] = c3; }
    __syncthreads();

    {
        const int cls = threadIdx.x >> 6;  // 0..3
        const int col = threadIdx.x & 63;  // 0..63
        float4 r  = s4[0][cls][col];
        float4 t1 = s4[1][cls][col];
        float4 t2 = s4[2][cls][col];
        float4 t3 = s4[3][cls][col];
        r.x += t1.x + t2.x + t3.x;
        r.y += t1.y + t2.y + t3.y;
        r.z += t1.z + t2.z + t3.z;
        r.w += t1.w + t2.w + t3.w;
        float* gs = &g_sums[cls * D + col * 4];
        atomicAdd(gs + 0, r.x); atomicAdd(gs + 1, r.y);
        atomicAdd(gs + 2, r.z); atomicAdd(gs + 3, r.w);
    }
    if (threadIdx.x < NCLS) {
        const int t = sc[0][threadIdx.x] + sc[1][threadIdx.x] +
                      sc[2][threadIdx.x] + sc[3][threadIdx.x];
        atomicAdd(&g_counts[threadIdx.x], t);
    }
}

// ---------------------------------------------------------------------------
// Mean, L2 normalize (eps 1e-12), write centers (+ target tail), then re-zero
// the scratch so the graph replay invariant holds.
// ---------------------------------------------------------------------------
__global__ void finalize_kernel(float* __restrict__ out, int out_size) {
    const int tid = threadIdx.x;   // 0..255 = column
    __shared__ float red[256];
    __shared__ float s_norm;

    for (int c = 0; c < NCLS; c++) {
        const float mean = g_sums[c * D + tid] / (float)g_counts[c];
        g_sums[c * D + tid] = 0.0f;               // restore invariant
        red[tid] = mean * mean;
        __syncthreads();
        #pragma unroll
        for (int off = 128; off > 0; off >>= 1) {
            if (tid < off) red[tid] += red[tid + off];
            __syncthreads();
        }
        if (tid == 0) s_norm = fmaxf(sqrtf(red[0]), 1e-12f);
        __syncthreads();
        out[c * D + tid] = mean / s_norm;
        __syncthreads();
    }
    if (tid < NCLS) g_counts[tid] = 0;            // restore invariant

    // Second output: target = arange(4) in the tail of d_out, if present.
    if (out_size > NCLS * D) {
        const int extra = out_size - NCLS * D;
        if (tid < extra) out[NCLS * D + tid] = (tid < NCLS) ? (float)tid : 0.0f;
    }
}

// ---------------------------------------------------------------------------
extern "C" void kernel_launch(void* const* d_in, const int* in_sizes, int n_in,
                              void* d_out, int out_size) {
    const float4*       feat = (const float4*)d_in[0];
    const unsigned int* labw = (const unsigned int*)d_in[1];
    const int rows = in_sizes[1];

    accum_kernel<<<1184, 256>>>(feat, labw, rows);
    finalize_kernel<<<1, 256>>>((float*)d_out, out_size);
}

// round 8
// speedup vs baseline: 1.2040x; 1.1764x over previous
#include <cuda_runtime.h>

#define D    256
#define NCLS 4
#define GRID 1184          // 148 SMs * 8
#define ROWS_PER_BLK_ITER 16

// Scratch: zero at kernel entry (zero-init at module load; the last block
// re-zeroes after consuming, so the invariant holds across graph replays).
__device__ float    g_sums[NCLS * D];
__device__ int      g_counts[NCLS];
__device__ unsigned g_done;

__global__ void __launch_bounds__(256) center_fused_kernel(
    const float4* __restrict__ feat,          // [rows, 64] float4
    const unsigned int* __restrict__ labw,    // label words (int32 or int64)
    int rows,
    float* __restrict__ out, int out_size)
{
    // ---- label width detection (int64 LE => odd words are zero high halves)
    __shared__ int s_ls;
    if (threadIdx.x < 32) {
        unsigned w = labw[2 * threadIdx.x + 1];
        unsigned any = __ballot_sync(0xffffffffu, w != 0u);
        if (threadIdx.x == 0) s_ls = any ? 1 : 2;
    }
    __syncthreads();
    const int ls = s_ls;

    const int x = threadIdx.x & 63;    // float4 column
    const int y = threadIdx.x >> 6;    // row lane 0..3 (uniform per warp)

    float4 a0 = make_float4(0.f, 0.f, 0.f, 0.f);
    float4 a1 = a0, a2 = a0, a3 = a0;
    int c0 = 0, c1 = 0, c2 = 0, c3 = 0;

    // Pointer-incremented main loop: no 64-bit muls inside.
    const long long r0 = (long long)blockIdx.x * ROWS_PER_BLK_ITER + y * 4;
    const long long S  = (long long)GRID * ROWS_PER_BLK_ITER;      // row stride
    const float4*       p  = feat + r0 * 64 + x;
    const unsigned int* lp = labw + r0 * ls;
    const long long pInc = S * 64;
    const long long lInc = (long long)S * ls;
    const int ls1 = ls, ls2 = 2 * ls, ls3 = 3 * ls;

#define ACCROW(v, l)                                                          \
        {                                                                     \
            const float w0 = ((l) == 0) ? 1.f : 0.f;                          \
            const float w1 = ((l) == 1) ? 1.f : 0.f;                          \
            const float w2 = ((l) == 2) ? 1.f : 0.f;                          \
            const float w3 = ((l) == 3) ? 1.f : 0.f;                          \
            a0.x = fmaf(v.x, w0, a0.x); a0.y = fmaf(v.y, w0, a0.y);           \
            a0.z = fmaf(v.z, w0, a0.z); a0.w = fmaf(v.w, w0, a0.w);           \
            a1.x = fmaf(v.x, w1, a1.x); a1.y = fmaf(v.y, w1, a1.y);           \
            a1.z = fmaf(v.z, w1, a1.z); a1.w = fmaf(v.w, w1, a1.w);           \
            a2.x = fmaf(v.x, w2, a2.x); a2.y = fmaf(v.y, w2, a2.y);           \
            a2.z = fmaf(v.z, w2, a2.z); a2.w = fmaf(v.w, w2, a2.w);           \
            a3.x = fmaf(v.x, w3, a3.x); a3.y = fmaf(v.y, w3, a3.y);           \
            a3.z = fmaf(v.z, w3, a3.z); a3.w = fmaf(v.w, w3, a3.w);           \
        }

    long long r = r0;
    for (; r + 4 <= rows; r += S, p += pInc, lp += lInc) {
        // 8 independent loads batched up front (streaming hints).
        const int l0 = (int)__ldcs(lp);
        const int l1 = (int)__ldcs(lp + ls1);
        const int l2 = (int)__ldcs(lp + ls2);
        const int l3 = (int)__ldcs(lp + ls3);
        const float4 v0 = __ldcs(p);
        const float4 v1 = __ldcs(p + 64);
        const float4 v2 = __ldcs(p + 128);
        const float4 v3 = __ldcs(p + 192);

        ACCROW(v0, l0) ACCROW(v1, l1) ACCROW(v2, l2) ACCROW(v3, l3)

        if (x == 0) {
            c0 += (l0 == 0) + (l1 == 0) + (l2 == 0) + (l3 == 0);
            c1 += (l0 == 1) + (l1 == 1) + (l2 == 1) + (l3 == 1);
            c2 += (l0 == 2) + (l1 == 2) + (l2 == 2) + (l3 == 2);
            c3 += (l0 == 3) + (l1 == 3) + (l2 == 3) + (l3 == 3);
        }
    }
    // Tail: up to 3 rows.
    for (int k = 0; r + k < rows && k < 4; k++) {
        const int    l = (int)__ldcs(lp + k * ls1);
        const float4 v = __ldcs(p + k * 64);
        ACCROW(v, l)
        if (x == 0) {
            c0 += (l == 0); c1 += (l == 1); c2 += (l == 2); c3 += (l == 3);
        }
    }
#undef ACCROW

    // ---- block reduction: unique smem slots, then 4 global atomics/thread.
    __shared__ float4 s4[4][NCLS][64];     // 16 KB
    __shared__ int    sc[4][NCLS];
    s4[y][0][x] = a0; s4[y][1][x] = a1; s4[y][2][x] = a2; s4[y][3][x] = a3;
    if (x == 0) { sc[y][0] = c0; sc[y][1] = c1; sc[y][2] = c2; sc[y][3] = c3; }
    __syncthreads();

    {
        const int cls = threadIdx.x >> 6;
        const int col = threadIdx.x & 63;
        float4 rr = s4[0][cls][col];
        float4 t1 = s4[1][cls][col];
        float4 t2 = s4[2][cls][col];
        float4 t3 = s4[3][cls][col];
        rr.x += t1.x + t2.x + t3.x;  rr.y += t1.y + t2.y + t3.y;
        rr.z += t1.z + t2.z + t3.z;  rr.w += t1.w + t2.w + t3.w;
        float* gs = &g_sums[cls * D + col * 4];
        atomicAdd(gs + 0, rr.x); atomicAdd(gs + 1, rr.y);
        atomicAdd(gs + 2, rr.z); atomicAdd(gs + 3, rr.w);
    }
    if (threadIdx.x < NCLS) {
        atomicAdd(&g_counts[threadIdx.x],
                  sc[0][threadIdx.x] + sc[1][threadIdx.x] +
                  sc[2][threadIdx.x] + sc[3][threadIdx.x]);
    }

    // ---- last block finalizes.
    __threadfence();
    __shared__ int s_last;
    if (threadIdx.x == 0)
        s_last = (atomicAdd(&g_done, 1u) == (unsigned)(gridDim.x - 1));
    __syncthreads();
    if (!s_last) return;

    const int tid = threadIdx.x;              // 0..255 = column
    __shared__ float red[256];
    __shared__ float s_norm;
    if (tid == 0) g_done = 0;                 // restore invariant

    for (int c = 0; c < NCLS; c++) {
        const float mean = g_sums[c * D + tid] / (float)g_counts[c];
        g_sums[c * D + tid] = 0.0f;           // restore invariant
        red[tid] = mean * mean;
        __syncthreads();
        #pragma unroll
        for (int off = 128; off > 0; off >>= 1) {
            if (tid < off) red[tid] += red[tid + off];
            __syncthreads();
        }
        if (tid == 0) s_norm = fmaxf(sqrtf(red[0]), 1e-12f);
        __syncthreads();
        out[c * D + tid] = mean / s_norm;
        __syncthreads();
    }
    if (tid < NCLS) g_counts[tid] = 0;        // restore invariant

    if (out_size > NCLS * D) {
        const int extra = out_size - NCLS * D;
        if (tid < extra) out[NCLS * D + tid] = (tid < NCLS) ? (float)tid : 0.0f;
    }
}

extern "C" void kernel_launch(void* const* d_in, const int* in_sizes, int n_in,
                              void* d_out, int out_size) {
    const float4*       feat = (const float4*)d_in[0];
    const unsigned int* labw = (const unsigned int*)d_in[1];
    const int rows = in_sizes[1];

    center_fused_kernel<<<GRID, 256>>>(feat, labw, rows,
                                       (float*)d_out, out_size);
}

// round 9
// speedup vs baseline: 1.3780x; 1.1445x over previous
#include <cuda_runtime.h>

#define D     256
#define NCLS  4
#define GRIDF 888            // 148 SMs * 6 resident blocks
#define RPB   16             // rows per block per iteration (4 y-lanes * 4 rows)

// Scratch: zero at kernel entry (zero-init at module load; the last block
// re-zeroes after consuming, so the invariant holds across graph replays).
__device__ float    g_sums[NCLS * D];
__device__ int      g_s1, g_s2, g_s3;    // label power sums (exact counts)
__device__ unsigned g_done;

__global__ void __launch_bounds__(256, 6) center_fused_kernel(
    const float4* __restrict__ feat,          // [rows, 64] float4
    const unsigned int* __restrict__ labw,    // label words (int32 or int64)
    int rows,
    float* __restrict__ out, int out_size)
{
    // ---- label width detection (int64 LE => odd words are zero high halves)
    __shared__ int s_ls;
    if (threadIdx.x < 32) {
        unsigned w = labw[2 * threadIdx.x + 1];
        unsigned any = __ballot_sync(0xffffffffu, w != 0u);
        if (threadIdx.x == 0) s_ls = any ? 1 : 2;
    }
    __syncthreads();
    const int ls = s_ls;

    const int x = threadIdx.x & 63;    // float4 column
    const int y = threadIdx.x >> 6;    // row lane 0..3 (uniform per warp)

    float4 a0 = make_float4(0.f, 0.f, 0.f, 0.f);
    float4 a1 = a0, a2 = a0, a3 = a0;
    int s1 = 0, s2 = 0, s3 = 0;        // power sums of labels seen

    // All-32-bit loop arithmetic (feat <= ~1.03GB, offsets fit in 32 bits).
    int r = blockIdx.x * RPB + y * 4;
    const int S = GRIDF * RPB;                       // row stride
    const float4*       p  = feat + (unsigned)r * 64u + (unsigned)x;
    const unsigned int* lp = labw + (unsigned)r * (unsigned)ls;
    const unsigned pInc = (unsigned)S * 64u;         // float4 elements
    const unsigned lInc = (unsigned)S * (unsigned)ls;
    const int ls1 = ls, ls2 = 2 * ls, ls3 = 3 * ls;

#define ACCROW(v, l)                                                          \
        {                                                                     \
            const float w0 = ((l) == 0) ? 1.f : 0.f;                          \
            const float w1 = ((l) == 1) ? 1.f : 0.f;                          \
            const float w2 = ((l) == 2) ? 1.f : 0.f;                          \
            const float w3 = ((l) == 3) ? 1.f : 0.f;                          \
            a0.x = fmaf(v.x, w0, a0.x); a0.y = fmaf(v.y, w0, a0.y);           \
            a0.z = fmaf(v.z, w0, a0.z); a0.w = fmaf(v.w, w0, a0.w);           \
            a1.x = fmaf(v.x, w1, a1.x); a1.y = fmaf(v.y, w1, a1.y);           \
            a1.z = fmaf(v.z, w1, a1.z); a1.w = fmaf(v.w, w1, a1.w);           \
            a2.x = fmaf(v.x, w2, a2.x); a2.y = fmaf(v.y, w2, a2.y);           \
            a2.z = fmaf(v.z, w2, a2.z); a2.w = fmaf(v.w, w2, a2.w);           \
            a3.x = fmaf(v.x, w3, a3.x); a3.y = fmaf(v.y, w3, a3.y);           \
            a3.z = fmaf(v.z, w3, a3.z); a3.w = fmaf(v.w, w3, a3.w);           \
        }

    #pragma unroll 1
    for (; r + 4 <= rows; r += S, p += pInc, lp += lInc) {
        // 8 independent loads batched up front.
        const int l0 = (int)__ldcs(lp);
        const int l1 = (int)__ldcs(lp + ls1);
        const int l2 = (int)__ldcs(lp + ls2);
        const int l3 = (int)__ldcs(lp + ls3);
        const float4 v0 = __ldcs(p);
        const float4 v1 = __ldcs(p + 64);
        const float4 v2 = __ldcs(p + 128);
        const float4 v3 = __ldcs(p + 192);

        ACCROW(v0, l0) ACCROW(v1, l1) ACCROW(v2, l2) ACCROW(v3, l3)

        // Power sums (all lanes compute identical values; labels broadcast).
        const int q0 = l0 * l0, q1 = l1 * l1, q2 = l2 * l2, q3 = l3 * l3;
        s1 += (l0 + l1) + (l2 + l3);
        s2 += (q0 + q1) + (q2 + q3);
        s3 += q0 * l0 + q1 * l1 + q2 * l2 + q3 * l3;
    }
    // Tail: up to 3 rows.
    for (int k = 0; r + k < rows && k < 4; k++) {
        const int    l = (int)__ldcs(lp + k * ls1);
        const float4 v = __ldcs(p + k * 64);
        ACCROW(v, l)
        s1 += l; s2 += l * l; s3 += l * l * l;
    }
#undef ACCROW

    // ---- block reduction: unique smem slots, then 4 global atomics/thread.
    __shared__ float4 s4[4][NCLS][64];     // 16 KB
    __shared__ int    sm[4][3];
    s4[y][0][x] = a0; s4[y][1][x] = a1; s4[y][2][x] = a2; s4[y][3][x] = a3;
    if (x == 0) { sm[y][0] = s1; sm[y][1] = s2; sm[y][2] = s3; }
    __syncthreads();

    {
        const int cls = threadIdx.x >> 6;
        const int col = threadIdx.x & 63;
        float4 rr = s4[0][cls][col];
        float4 t1 = s4[1][cls][col];
        float4 t2 = s4[2][cls][col];
        float4 t3 = s4[3][cls][col];
        rr.x += t1.x + t2.x + t3.x;  rr.y += t1.y + t2.y + t3.y;
        rr.z += t1.z + t2.z + t3.z;  rr.w += t1.w + t2.w + t3.w;
        float* gs = &g_sums[cls * D + col * 4];
        atomicAdd(gs + 0, rr.x); atomicAdd(gs + 1, rr.y);
        atomicAdd(gs + 2, rr.z); atomicAdd(gs + 3, rr.w);
    }
    if (threadIdx.x == 0) {
        atomicAdd(&g_s1, sm[0][0] + sm[1][0] + sm[2][0] + sm[3][0]);
        atomicAdd(&g_s2, sm[0][1] + sm[1][1] + sm[2][1] + sm[3][1]);
        atomicAdd(&g_s3, sm[0][2] + sm[1][2] + sm[2][2] + sm[3][2]);
    }

    // ---- last block finalizes.
    __threadfence();
    __shared__ int s_last;
    if (threadIdx.x == 0)
        s_last = (atomicAdd(&g_done, 1u) == (unsigned)(gridDim.x - 1));
    __syncthreads();
    if (!s_last) return;

    const int tid = threadIdx.x;              // 0..255 = column
    __shared__ float red[256];
    __shared__ float s_norm;
    __shared__ float s_cnt[NCLS];

    if (tid == 0) {
        // Recover exact per-class counts from power sums (Vandermonde).
        const int S1 = g_s1, S2 = g_s2, S3 = g_s3;
        const int n3 = (S3 - 3 * S2 + 2 * S1) / 6;
        const int n2 = (S2 - S1 - 6 * n3) / 2;
        const int n1 = S1 - 2 * n2 - 3 * n3;
        const int n0 = rows - n1 - n2 - n3;
        s_cnt[0] = (float)n0; s_cnt[1] = (float)n1;
        s_cnt[2] = (float)n2; s_cnt[3] = (float)n3;
        g_s1 = 0; g_s2 = 0; g_s3 = 0; g_done = 0;   // restore invariant
    }
    __syncthreads();

    for (int c = 0; c < NCLS; c++) {
        const float mean = g_sums[c * D + tid] / s_cnt[c];
        g_sums[c * D + tid] = 0.0f;           // restore invariant
        red[tid] = mean * mean;
        __syncthreads();
        #pragma unroll
        for (int off = 128; off > 0; off >>= 1) {
            if (tid < off) red[tid] += red[tid + off];
            __syncthreads();
        }
        if (tid == 0) s_norm = fmaxf(sqrtf(red[0]), 1e-12f);
        __syncthreads();
        out[c * D + tid] = mean / s_norm;
        __syncthreads();
    }

    if (out_size > NCLS * D) {
        const int extra = out_size - NCLS * D;
        if (tid < extra) out[NCLS * D + tid] = (tid < NCLS) ? (float)tid : 0.0f;
    }
}

extern "C" void kernel_launch(void* const* d_in, const int* in_sizes, int n_in,
                              void* d_out, int out_size) {
    const float4*       feat = (const float4*)d_in[0];
    const unsigned int* labw = (const unsigned int*)d_in[1];
    const int rows = in_sizes[1];

    center_fused_kernel<<<GRIDF, 256>>>(feat, labw, rows,
                                        (float*)d_out, out_size);
}